// round 14
// baseline (speedup 1.0000x reference)
#include <cuda_runtime.h>
#include <math.h>

#define N_NODES 50000
#define N_EDGES 800000
#define F_IN    32
#define H_DIM   64
#define C_OUT   7
#define C_PAD   8
#define BN_EPS  1e-5f

// ---------------- scratch (device globals; no allocation) ----------------
__device__ __align__(128) float g_Y0[N_NODES * H_DIM];   // h @ (W0*k)
__device__ __align__(128) float g_Y1[N_NODES * H_DIM];   // h @ ((W1-W0)*k)
__device__ __align__(128) float g_Z [N_NODES * H_DIM];   // h @ (R*k) + bias'
__device__ __align__(128) float g_A [N_NODES * H_DIM];   // aggregation accumulator
__device__ __align__(128) float g_H [N_NODES * H_DIM];   // hidden activations
__device__ __align__(128) float g_ST[2 * N_NODES * F_IN];// L0 input-space accumulators: S | T
__device__ __align__(128) int   g_cnt[N_NODES];          // in-degree
// folded weights, TRANSPOSED [o][c] layout per block: [w0 | dw | r]
__device__ __align__(16)  float g_WT0[3 * H_DIM * F_IN];
__device__ __align__(16)  float g_WT1[3 * H_DIM * H_DIM];
__device__ __align__(16)  float g_WT2[3 * C_OUT * H_DIM];
__device__ __align__(16)  float g_TB0[H_DIM];
__device__ __align__(16)  float g_TB1[H_DIM];
__device__ __align__(16)  float g_TB2[C_OUT];

// ---------------- prep: zero g_cnt + fold BN + transpose weights ----------------
__device__ __forceinline__ void fold_one(const float* W, const float* R, const float* B,
                                         const float* G, const float* BE,
                                         const float* RM, const float* RV,
                                         float* WT, float* TB, int cin, int cout, int t)
{
    int c = t / cout, o = t % cout;
    float k = 1.f, sh = 0.f;
    if (G) {
        k  = G[o] * rsqrtf(RV[o] + BN_EPS);
        sh = BE[o] - RM[o] * k;
    }
    float w0 = W[c * cout + o];
    float w1 = W[cin * cout + c * cout + o];
    WT[o * cin + c]                  = w0 * k;
    WT[cout * cin + o * cin + c]     = (w1 - w0) * k;
    WT[2 * cout * cin + o * cin + c] = R[c * cout + o] * k;
    if (c == 0) TB[o] = B[o] * k + sh;
}

__global__ void prep_kernel(const float* __restrict__ W0, const float* __restrict__ R0, const float* __restrict__ B0,
                            const float* __restrict__ W1, const float* __restrict__ R1, const float* __restrict__ B1,
                            const float* __restrict__ W2, const float* __restrict__ R2, const float* __restrict__ B2,
                            const float* __restrict__ G0, const float* __restrict__ BE0,
                            const float* __restrict__ RM0, const float* __restrict__ RV0,
                            const float* __restrict__ G1, const float* __restrict__ BE1,
                            const float* __restrict__ RM1, const float* __restrict__ RV1)
{
    int t = blockIdx.x * blockDim.x + threadIdx.x;
    if (t < N_NODES) g_cnt[t] = 0;

    const int S0 = F_IN * H_DIM;            // 2048
    const int S1 = S0 + H_DIM * H_DIM;      // 6144
    const int S2 = S1 + H_DIM * C_OUT;      // 6592
    if (t < S0) {
        fold_one(W0, R0, B0, G0, BE0, RM0, RV0, g_WT0, g_TB0, F_IN,  H_DIM, t);
    } else if (t < S1) {
        fold_one(W1, R1, B1, G1, BE1, RM1, RV1, g_WT1, g_TB1, H_DIM, H_DIM, t - S0);
    } else if (t < S2) {
        fold_one(W2, R2, B2, nullptr, nullptr, nullptr, nullptr, g_WT2, g_TB2, H_DIM, C_OUT, t - S1);
    }
}

// degree histogram + zero S/T (800k threads exactly cover the 800k float4 of g_ST)
__global__ void deg_kernel(const int* __restrict__ ei) {
    int e = blockIdx.x * blockDim.x + threadIdx.x;
    if (e < N_EDGES) {
        atomicAdd(&g_cnt[ei[N_EDGES + e]], 1);
        reinterpret_cast<float4*>(g_ST)[e] = make_float4(0.f, 0.f, 0.f, 0.f);
    }
}

// ---------------- L0 edge scatter in INPUT space: S[d]+=x[s], T[d]+=u*x[s] ----------------
__global__ void __launch_bounds__(256)
scatter_x_kernel(const int* __restrict__ ei, const float* __restrict__ ea,
                 const float* __restrict__ X)
{
    constexpr int Q = F_IN / 4;   // 8
    int idx = blockIdx.x * blockDim.x + threadIdx.x;
    if (idx >= N_EDGES * Q) return;
    int e = idx >> 3;
    int q = idx & 7;

    int   s = ei[e];
    int   d = ei[N_EDGES + e];
    float u = ea[e];

    float4 v = reinterpret_cast<const float4*>(X)[s * Q + q];
    float4 t;
    t.x = u * v.x; t.y = u * v.y; t.z = u * v.z; t.w = u * v.w;

    float* ps = &g_ST[d * F_IN + q * 4];
    float* pt = &g_ST[N_NODES * F_IN + d * F_IN + q * 4];
    asm volatile("red.global.add.v4.f32 [%0], {%1,%2,%3,%4};"
                 :: "l"(ps), "f"(v.x), "f"(v.y), "f"(v.z), "f"(v.w) : "memory");
    asm volatile("red.global.add.v4.f32 [%0], {%1,%2,%3,%4};"
                 :: "l"(pt), "f"(t.x), "f"(t.y), "f"(t.z), "f"(t.w) : "memory");
}

// ---------------- L0 fused node GEMM (vectorized): h = ELU(S'@W0k + T'@dWk + x@Rk + b) ----------------
// S', T' pre-scaled by 1/deg during staging -> single accumulator per (node, o)
__global__ void __launch_bounds__(256)
gemm_l0_kernel(const float* __restrict__ X)
{
    __shared__ float ss[32][F_IN];
    __shared__ float st[32][F_IN];
    __shared__ float sx[32][F_IN];

    int nbase = blockIdx.x * 32;
    int tid = threadIdx.y * 64 + threadIdx.x;

    const float4* S4 = reinterpret_cast<const float4*>(g_ST);
    const float4* T4 = reinterpret_cast<const float4*>(g_ST + N_NODES * F_IN);
    const float4* X4 = reinterpret_cast<const float4*>(X);
    {
        int row = tid >> 3, q = tid & 7;
        int n = nbase + row;
        float4 vs = make_float4(0.f,0.f,0.f,0.f), vt = vs, vx = vs;
        if (n < N_NODES) {
            int cnt = g_cnt[n];
            float inv = 1.f / (float)(cnt < 1 ? 1 : cnt);
            vs = S4[n * 8 + q];
            vt = T4[n * 8 + q];
            vx = X4[n * 8 + q];
            vs.x *= inv; vs.y *= inv; vs.z *= inv; vs.w *= inv;
            vt.x *= inv; vt.y *= inv; vt.z *= inv; vt.w *= inv;
        }
        *reinterpret_cast<float4*>(&ss[row][q * 4]) = vs;
        *reinterpret_cast<float4*>(&st[row][q * 4]) = vt;
        *reinterpret_cast<float4*>(&sx[row][q * 4]) = vx;
    }
    __syncthreads();

    int o  = threadIdx.x;          // 0..63
    int nb = threadIdx.y * 8;      // 8 nodes per thread

    float a[8];
    #pragma unroll
    for (int j = 0; j < 8; j++) a[j] = 0.f;

    const float4* w0p = reinterpret_cast<const float4*>(g_WT0 + o * F_IN);
    const float4* dwp = reinterpret_cast<const float4*>(g_WT0 + H_DIM * F_IN + o * F_IN);
    const float4* rp  = reinterpret_cast<const float4*>(g_WT0 + 2 * H_DIM * F_IN + o * F_IN);

    #pragma unroll
    for (int cq = 0; cq < F_IN / 4; cq++) {
        float4 w0 = w0p[cq];
        float4 dw = dwp[cq];
        float4 r  = rp[cq];
        #pragma unroll
        for (int j = 0; j < 8; j++) {
            float4 s4 = *reinterpret_cast<const float4*>(&ss[nb + j][cq * 4]);
            float4 t4 = *reinterpret_cast<const float4*>(&st[nb + j][cq * 4]);
            float4 x4 = *reinterpret_cast<const float4*>(&sx[nb + j][cq * 4]);
            float acc = a[j];
            acc = fmaf(s4.x, w0.x, acc); acc = fmaf(s4.y, w0.y, acc);
            acc = fmaf(s4.z, w0.z, acc); acc = fmaf(s4.w, w0.w, acc);
            acc = fmaf(t4.x, dw.x, acc); acc = fmaf(t4.y, dw.y, acc);
            acc = fmaf(t4.z, dw.z, acc); acc = fmaf(t4.w, dw.w, acc);
            acc = fmaf(x4.x, r.x,  acc); acc = fmaf(x4.y, r.y,  acc);
            acc = fmaf(x4.z, r.z,  acc); acc = fmaf(x4.w, r.w,  acc);
            a[j] = acc;
        }
    }

    float b = g_TB0[o];
    #pragma unroll
    for (int j = 0; j < 8; j++) {
        int n = nbase + nb + j;
        if (n < N_NODES) {
            float v = a[j] + b;
            v = (v > 0.f) ? v : expm1f(v);
            g_H[n * H_DIM + o] = v;
        }
    }
}

// ---------------- fused node GEMM (vectorized): Y0, Y1, Z; zeroes g_A ----------------
template<int CIN, int COUT, int COUTP, int NT>
__global__ void __launch_bounds__(256)
gemm3_kernel(int sel)
{
    constexpr int TY    = 256 / COUTP;
    constexpr int NODES = TY * NT;
    __shared__ float sx[NODES][CIN];

    const float* WT = (sel == 1) ? g_WT1 : g_WT2;
    const float* TB = (sel == 1) ? g_TB1 : g_TB2;
    const float* X  = (const float*)g_H;

    int nbase = blockIdx.x * NODES;
    int tid = threadIdx.y * COUTP + threadIdx.x;

    constexpr int NV = NODES * CIN / 4;
    const float4* X4 = reinterpret_cast<const float4*>(X);
    float4* sx4 = reinterpret_cast<float4*>(&sx[0][0]);
    #pragma unroll
    for (int i = tid; i < NV; i += 256) {
        int nn = nbase + i / (CIN / 4);
        float4 v = make_float4(0.f, 0.f, 0.f, 0.f);
        if (nn < N_NODES) v = X4[nn * (CIN / 4) + (i % (CIN / 4))];
        sx4[i] = v;
    }
    __syncthreads();

    int o  = threadIdx.x;
    int nb = threadIdx.y * NT;

    float a0[NT], a1[NT], az[NT];
    #pragma unroll
    for (int j = 0; j < NT; j++) { a0[j] = 0.f; a1[j] = 0.f; az[j] = 0.f; }

    float b = 0.f;
    if (o < COUT) {
        b = TB[o];
        const float4* w0p = reinterpret_cast<const float4*>(WT + o * CIN);
        const float4* dwp = reinterpret_cast<const float4*>(WT + COUT * CIN + o * CIN);
        const float4* rp  = reinterpret_cast<const float4*>(WT + 2 * COUT * CIN + o * CIN);
        #pragma unroll 4
        for (int cq = 0; cq < CIN / 4; cq++) {
            float4 w0 = w0p[cq];
            float4 dw = dwp[cq];
            float4 r  = rp[cq];
            #pragma unroll
            for (int j = 0; j < NT; j++) {
                float4 xv = *reinterpret_cast<const float4*>(&sx[nb + j][cq * 4]);
                float c0 = a0[j], c1 = a1[j], cz = az[j];
                c0 = fmaf(xv.x, w0.x, c0); c0 = fmaf(xv.y, w0.y, c0);
                c0 = fmaf(xv.z, w0.z, c0); c0 = fmaf(xv.w, w0.w, c0);
                c1 = fmaf(xv.x, dw.x, c1); c1 = fmaf(xv.y, dw.y, c1);
                c1 = fmaf(xv.z, dw.z, c1); c1 = fmaf(xv.w, dw.w, c1);
                cz = fmaf(xv.x, r.x,  cz); cz = fmaf(xv.y, r.y,  cz);
                cz = fmaf(xv.z, r.z,  cz); cz = fmaf(xv.w, r.w,  cz);
                a0[j] = c0; a1[j] = c1; az[j] = cz;
            }
        }
    }

    #pragma unroll
    for (int j = 0; j < NT; j++) {
        int n = nbase + nb + j;
        if (n < N_NODES) {
            g_Y0[n * COUTP + o] = a0[j];
            g_Y1[n * COUTP + o] = a1[j];
            g_Z [n * COUTP + o] = az[j] + b;   // pad cols exact 0
            g_A [n * COUTP + o] = 0.f;
        }
    }
}

// ---------------- flat edge scatter (proven): A[dst] += Y0[src] + u*Y1[src] ----------------
template<int COUTP>
__global__ void __launch_bounds__(256)
scatter_kernel(const int* __restrict__ ei, const float* __restrict__ ea)
{
    constexpr int Q = COUTP / 4;
    int idx = blockIdx.x * blockDim.x + threadIdx.x;
    if (idx >= N_EDGES * Q) return;
    int e = idx / Q;           // power-of-2 -> shift
    int q = idx - e * Q;

    int   s = ei[e];
    int   d = ei[N_EDGES + e];
    float u = ea[e];

    const float4* Y04 = reinterpret_cast<const float4*>(g_Y0);
    const float4* Y14 = reinterpret_cast<const float4*>(g_Y1);
    float4 v0 = Y04[s * Q + q];
    float4 v1 = Y14[s * Q + q];
    float4 m;
    m.x = fmaf(u, v1.x, v0.x);
    m.y = fmaf(u, v1.y, v0.y);
    m.z = fmaf(u, v1.z, v0.z);
    m.w = fmaf(u, v1.w, v0.w);

    float* dst = &g_A[d * COUTP + q * 4];
    asm volatile("red.global.add.v4.f32 [%0], {%1,%2,%3,%4};"
                 :: "l"(dst), "f"(m.x), "f"(m.y), "f"(m.z), "f"(m.w) : "memory");
}

// ---------------- epilogue: mean + residual (BN pre-folded) + ELU -> g_H ----------------
__global__ void __launch_bounds__(256)
epi_kernel()
{
    int i4 = blockIdx.x * blockDim.x + threadIdx.x;
    if (i4 >= N_NODES * (H_DIM / 4)) return;
    int n = i4 >> 4;

    int cnt = g_cnt[n];
    float inv = 1.f / (float)(cnt < 1 ? 1 : cnt);

    float4 a = reinterpret_cast<const float4*>(g_A)[i4];
    float4 z = reinterpret_cast<const float4*>(g_Z)[i4];

    float4 v;
    v.x = fmaf(a.x, inv, z.x);
    v.y = fmaf(a.y, inv, z.y);
    v.z = fmaf(a.z, inv, z.z);
    v.w = fmaf(a.w, inv, z.w);
    v.x = (v.x > 0.f) ? v.x : expm1f(v.x);
    v.y = (v.y > 0.f) ? v.y : expm1f(v.y);
    v.z = (v.z > 0.f) ? v.z : expm1f(v.z);
    v.w = (v.w > 0.f) ? v.w : expm1f(v.w);

    reinterpret_cast<float4*>(g_H)[i4] = v;
}

// ---------------- final: mean + residual + log_softmax (8 lanes per node) ----------------
__global__ void __launch_bounds__(256)
final_kernel(float* __restrict__ out)
{
    int t    = blockIdx.x * blockDim.x + threadIdx.x;
    int node = t >> 3;
    int o    = t & 7;
    if (node >= N_NODES) return;

    int cnt = g_cnt[node];
    float inv = 1.f / (float)(cnt < 1 ? 1 : cnt);
    float v = g_A[node * C_PAD + o] * inv + g_Z[node * C_PAD + o];

    float vm = (o < C_OUT) ? v : -INFINITY;
    float mx = vm;
    #pragma unroll
    for (int d = 1; d < 8; d <<= 1)
        mx = fmaxf(mx, __shfl_xor_sync(0xFFFFFFFFu, mx, d));

    float ex = (o < C_OUT) ? __expf(v - mx) : 0.f;
    float s  = ex;
    #pragma unroll
    for (int d = 1; d < 8; d <<= 1)
        s += __shfl_xor_sync(0xFFFFFFFFu, s, d);

    float lse = mx + logf(s);
    if (o < C_OUT) out[node * C_OUT + o] = v - lse;
}

// ---------------- launch ----------------
extern "C" void kernel_launch(void* const* d_in, const int* in_sizes, int n_in,
                              void* d_out, int out_size)
{
    const float* x   = (const float*)d_in[0];
    const int*   ei  = (const int*)  d_in[1];
    const float* ea  = (const float*)d_in[2];
    const float* W0  = (const float*)d_in[3];
    const float* R0  = (const float*)d_in[4];
    const float* B0  = (const float*)d_in[5];
    const float* W1  = (const float*)d_in[6];
    const float* R1  = (const float*)d_in[7];
    const float* B1  = (const float*)d_in[8];
    const float* W2  = (const float*)d_in[9];
    const float* R2  = (const float*)d_in[10];
    const float* B2  = (const float*)d_in[11];
    const float* G0  = (const float*)d_in[12];
    const float* BE0 = (const float*)d_in[13];
    const float* RM0 = (const float*)d_in[14];
    const float* RV0 = (const float*)d_in[15];
    const float* G1  = (const float*)d_in[16];
    const float* BE1 = (const float*)d_in[17];
    const float* RM1 = (const float*)d_in[18];
    const float* RV1 = (const float*)d_in[19];
    float* out = (float*)d_out;

    // prologue
    prep_kernel<<<(N_NODES + 255) / 256, 256>>>(W0, R0, B0, W1, R1, B1, W2, R2, B2,
                                                G0, BE0, RM0, RV0, G1, BE1, RM1, RV1);
    deg_kernel<<<(N_EDGES + 255) / 256, 256>>>(ei);

    // ---- Layer 0: input-space scatter (32-dim), then fused GEMM+mean+BN+ELU ----
    scatter_x_kernel<<<(N_EDGES * 8 + 255) / 256, 256>>>(ei, ea, x);
    gemm_l0_kernel<<<(N_NODES + 31) / 32, dim3(64, 4)>>>(x);

    // ---- Layer 1: 64 -> 64 (output-space) ----
    gemm3_kernel<64, 64, 64, 8><<<(N_NODES + 31) / 32, dim3(64, 4)>>>(1);
    scatter_kernel<64><<<(N_EDGES * 16 + 255) / 256, 256>>>(ei, ea);
    epi_kernel<<<(N_NODES * 16 + 255) / 256, 256>>>();

    // ---- Layer 2: 64 -> 7 (pad 8) ----
    gemm3_kernel<64, 7, 8, 2><<<(N_NODES + 63) / 64, dim3(8, 32)>>>(2);
    scatter_kernel<8><<<(N_EDGES * 2 + 255) / 256, 256>>>(ei, ea);
    final_kernel<<<(N_NODES * 8 + 255) / 256, 256>>>(out);
}

// round 15
// speedup vs baseline: 1.5239x; 1.5239x over previous
#include <cuda_runtime.h>
#include <math.h>

#define N_NODES 50000
#define N_EDGES 800000
#define F_IN    32
#define H_DIM   64
#define C_OUT   7
#define C_PAD   8
#define BN_EPS  1e-5f

// ---------------- scratch (device globals; no allocation) ----------------
__device__ __align__(128) float g_Y0[N_NODES * H_DIM];   // h @ (W0*k)
__device__ __align__(128) float g_Y1[N_NODES * H_DIM];   // h @ ((W1-W0)*k)
__device__ __align__(128) float g_Z [N_NODES * H_DIM];   // h @ (R*k) + bias'
__device__ __align__(128) float g_A [N_NODES * H_DIM];   // aggregation accumulator
__device__ __align__(128) float g_H [N_NODES * H_DIM];   // hidden activations
__device__ __align__(128) float g_ST[2 * N_NODES * F_IN];// L0 input-space accumulators: S | T
__device__ __align__(128) int   g_cnt[N_NODES];          // in-degree
// folded weights, PACKED layout per block: [cq][o][4]  (4 consecutive c's per o, contiguous)
__device__ __align__(16)  float g_WP0[3 * F_IN  * H_DIM];
__device__ __align__(16)  float g_WP1[3 * H_DIM * H_DIM];
__device__ __align__(16)  float g_WP2[3 * H_DIM * C_OUT];
__device__ __align__(16)  float g_TB0[H_DIM];
__device__ __align__(16)  float g_TB1[H_DIM];
__device__ __align__(16)  float g_TB2[C_OUT];

// ---------------- prep: zero g_cnt + fold BN + pack weights ----------------
// packed index: WP[blk][cq*cout*4 + o*4 + (c&3)]
__device__ __forceinline__ void fold_one(const float* W, const float* R, const float* B,
                                         const float* G, const float* BE,
                                         const float* RM, const float* RV,
                                         float* WP, float* TB, int cin, int cout, int t)
{
    int c = t / cout, o = t % cout;
    float k = 1.f, sh = 0.f;
    if (G) {
        k  = G[o] * rsqrtf(RV[o] + BN_EPS);
        sh = BE[o] - RM[o] * k;
    }
    float w0 = W[c * cout + o];
    float w1 = W[cin * cout + c * cout + o];
    int pi = (c >> 2) * cout * 4 + o * 4 + (c & 3);
    WP[pi]                  = w0 * k;
    WP[cin * cout + pi]     = (w1 - w0) * k;
    WP[2 * cin * cout + pi] = R[c * cout + o] * k;
    if (c == 0) TB[o] = B[o] * k + sh;
}

__global__ void prep_kernel(const float* __restrict__ W0, const float* __restrict__ R0, const float* __restrict__ B0,
                            const float* __restrict__ W1, const float* __restrict__ R1, const float* __restrict__ B1,
                            const float* __restrict__ W2, const float* __restrict__ R2, const float* __restrict__ B2,
                            const float* __restrict__ G0, const float* __restrict__ BE0,
                            const float* __restrict__ RM0, const float* __restrict__ RV0,
                            const float* __restrict__ G1, const float* __restrict__ BE1,
                            const float* __restrict__ RM1, const float* __restrict__ RV1)
{
    int t = blockIdx.x * blockDim.x + threadIdx.x;
    if (t < N_NODES) g_cnt[t] = 0;

    const int S0 = F_IN * H_DIM;            // 2048
    const int S1 = S0 + H_DIM * H_DIM;      // 6144
    const int S2 = S1 + H_DIM * C_OUT;      // 6592
    if (t < S0) {
        fold_one(W0, R0, B0, G0, BE0, RM0, RV0, g_WP0, g_TB0, F_IN,  H_DIM, t);
    } else if (t < S1) {
        fold_one(W1, R1, B1, G1, BE1, RM1, RV1, g_WP1, g_TB1, H_DIM, H_DIM, t - S0);
    } else if (t < S2) {
        fold_one(W2, R2, B2, nullptr, nullptr, nullptr, nullptr, g_WP2, g_TB2, H_DIM, C_OUT, t - S1);
    }
}

// degree histogram + zero S/T (800k threads exactly cover the 800k float4 of g_ST)
__global__ void deg_kernel(const int* __restrict__ ei) {
    int e = blockIdx.x * blockDim.x + threadIdx.x;
    if (e < N_EDGES) {
        atomicAdd(&g_cnt[ei[N_EDGES + e]], 1);
        reinterpret_cast<float4*>(g_ST)[e] = make_float4(0.f, 0.f, 0.f, 0.f);
    }
}

// ---------------- L0 edge scatter in INPUT space: S[d]+=x[s], T[d]+=u*x[s] ----------------
__global__ void __launch_bounds__(256)
scatter_x_kernel(const int* __restrict__ ei, const float* __restrict__ ea,
                 const float* __restrict__ X)
{
    constexpr int Q = F_IN / 4;   // 8
    int idx = blockIdx.x * blockDim.x + threadIdx.x;
    if (idx >= N_EDGES * Q) return;
    int e = idx >> 3;
    int q = idx & 7;

    int   s = ei[e];
    int   d = ei[N_EDGES + e];
    float u = ea[e];

    float4 v = reinterpret_cast<const float4*>(X)[s * Q + q];
    float4 t;
    t.x = u * v.x; t.y = u * v.y; t.z = u * v.z; t.w = u * v.w;

    float* ps = &g_ST[d * F_IN + q * 4];
    float* pt = &g_ST[N_NODES * F_IN + d * F_IN + q * 4];
    asm volatile("red.global.add.v4.f32 [%0], {%1,%2,%3,%4};"
                 :: "l"(ps), "f"(v.x), "f"(v.y), "f"(v.z), "f"(v.w) : "memory");
    asm volatile("red.global.add.v4.f32 [%0], {%1,%2,%3,%4};"
                 :: "l"(pt), "f"(t.x), "f"(t.y), "f"(t.z), "f"(t.w) : "memory");
}

// ---------------- L0 fused node GEMM: h = ELU(S'@W0k + T'@dWk + x@Rk + b) ----------------
// S', T' pre-scaled by 1/deg during staging -> single accumulator per (node, o)
__global__ void __launch_bounds__(256)
gemm_l0_kernel(const float* __restrict__ X)
{
    __shared__ float ss[32][F_IN];
    __shared__ float st[32][F_IN];
    __shared__ float sx[32][F_IN];

    int nbase = blockIdx.x * 32;
    int tid = threadIdx.y * 64 + threadIdx.x;

    const float4* S4 = reinterpret_cast<const float4*>(g_ST);
    const float4* T4 = reinterpret_cast<const float4*>(g_ST + N_NODES * F_IN);
    const float4* X4 = reinterpret_cast<const float4*>(X);
    {
        int row = tid >> 3, q = tid & 7;
        int n = nbase + row;
        float4 vs = make_float4(0.f,0.f,0.f,0.f), vt = vs, vx = vs;
        if (n < N_NODES) {
            int cnt = g_cnt[n];
            float inv = 1.f / (float)(cnt < 1 ? 1 : cnt);
            vs = S4[n * 8 + q];
            vt = T4[n * 8 + q];
            vx = X4[n * 8 + q];
            vs.x *= inv; vs.y *= inv; vs.z *= inv; vs.w *= inv;
            vt.x *= inv; vt.y *= inv; vt.z *= inv; vt.w *= inv;
        }
        *reinterpret_cast<float4*>(&ss[row][q * 4]) = vs;
        *reinterpret_cast<float4*>(&st[row][q * 4]) = vt;
        *reinterpret_cast<float4*>(&sx[row][q * 4]) = vx;
    }
    __syncthreads();

    int o  = threadIdx.x;          // 0..63
    int nb = threadIdx.y * 8;      // 8 nodes per thread

    float a[8];
    #pragma unroll
    for (int j = 0; j < 8; j++) a[j] = 0.f;

    // packed weights: float4 at index cq*H_DIM + o  -> coalesced LDG.128 across lanes
    const float4* w0p = reinterpret_cast<const float4*>(g_WP0);
    const float4* dwp = reinterpret_cast<const float4*>(g_WP0 + H_DIM * F_IN);
    const float4* rp  = reinterpret_cast<const float4*>(g_WP0 + 2 * H_DIM * F_IN);

    #pragma unroll
    for (int cq = 0; cq < F_IN / 4; cq++) {
        float4 w0 = w0p[cq * H_DIM + o];
        float4 dw = dwp[cq * H_DIM + o];
        float4 r  = rp [cq * H_DIM + o];
        #pragma unroll
        for (int j = 0; j < 8; j++) {
            float4 s4 = *reinterpret_cast<const float4*>(&ss[nb + j][cq * 4]);
            float4 t4 = *reinterpret_cast<const float4*>(&st[nb + j][cq * 4]);
            float4 x4 = *reinterpret_cast<const float4*>(&sx[nb + j][cq * 4]);
            float acc = a[j];
            acc = fmaf(s4.x, w0.x, acc); acc = fmaf(s4.y, w0.y, acc);
            acc = fmaf(s4.z, w0.z, acc); acc = fmaf(s4.w, w0.w, acc);
            acc = fmaf(t4.x, dw.x, acc); acc = fmaf(t4.y, dw.y, acc);
            acc = fmaf(t4.z, dw.z, acc); acc = fmaf(t4.w, dw.w, acc);
            acc = fmaf(x4.x, r.x,  acc); acc = fmaf(x4.y, r.y,  acc);
            acc = fmaf(x4.z, r.z,  acc); acc = fmaf(x4.w, r.w,  acc);
            a[j] = acc;
        }
    }

    float b = g_TB0[o];
    #pragma unroll
    for (int j = 0; j < 8; j++) {
        int n = nbase + nb + j;
        if (n < N_NODES) {
            float v = a[j] + b;
            v = (v > 0.f) ? v : expm1f(v);
            g_H[n * H_DIM + o] = v;
        }
    }
}

// ---------------- fused node GEMM (packed weights): Y0, Y1, Z; zeroes g_A ----------------
template<int CIN, int COUT, int COUTP, int NT>
__global__ void __launch_bounds__(256)
gemm3_kernel(int sel)
{
    constexpr int TY    = 256 / COUTP;
    constexpr int NODES = TY * NT;
    __shared__ float sx[NODES][CIN];

    const float* WP = (sel == 1) ? g_WP1 : g_WP2;
    const float* TB = (sel == 1) ? g_TB1 : g_TB2;
    const float* X  = (const float*)g_H;

    int nbase = blockIdx.x * NODES;
    int tid = threadIdx.y * COUTP + threadIdx.x;

    constexpr int NV = NODES * CIN / 4;
    const float4* X4 = reinterpret_cast<const float4*>(X);
    float4* sx4 = reinterpret_cast<float4*>(&sx[0][0]);
    #pragma unroll
    for (int i = tid; i < NV; i += 256) {
        int nn = nbase + i / (CIN / 4);
        float4 v = make_float4(0.f, 0.f, 0.f, 0.f);
        if (nn < N_NODES) v = X4[nn * (CIN / 4) + (i % (CIN / 4))];
        sx4[i] = v;
    }
    __syncthreads();

    int o  = threadIdx.x;
    int nb = threadIdx.y * NT;

    float a0[NT], a1[NT], az[NT];
    #pragma unroll
    for (int j = 0; j < NT; j++) { a0[j] = 0.f; a1[j] = 0.f; az[j] = 0.f; }

    float b = 0.f;
    if (o < COUT) {
        b = TB[o];
        const float4* w0p = reinterpret_cast<const float4*>(WP);
        const float4* dwp = reinterpret_cast<const float4*>(WP + CIN * COUT);
        const float4* rp  = reinterpret_cast<const float4*>(WP + 2 * CIN * COUT);
        #pragma unroll 4
        for (int cq = 0; cq < CIN / 4; cq++) {
            float4 w0 = w0p[cq * COUT + o];
            float4 dw = dwp[cq * COUT + o];
            float4 r  = rp [cq * COUT + o];
            #pragma unroll
            for (int j = 0; j < NT; j++) {
                float4 xv = *reinterpret_cast<const float4*>(&sx[nb + j][cq * 4]);
                float c0 = a0[j], c1 = a1[j], cz = az[j];
                c0 = fmaf(xv.x, w0.x, c0); c0 = fmaf(xv.y, w0.y, c0);
                c0 = fmaf(xv.z, w0.z, c0); c0 = fmaf(xv.w, w0.w, c0);
                c1 = fmaf(xv.x, dw.x, c1); c1 = fmaf(xv.y, dw.y, c1);
                c1 = fmaf(xv.z, dw.z, c1); c1 = fmaf(xv.w, dw.w, c1);
                cz = fmaf(xv.x, r.x,  cz); cz = fmaf(xv.y, r.y,  cz);
                cz = fmaf(xv.z, r.z,  cz); cz = fmaf(xv.w, r.w,  cz);
                a0[j] = c0; a1[j] = c1; az[j] = cz;
            }
        }
    }

    #pragma unroll
    for (int j = 0; j < NT; j++) {
        int n = nbase + nb + j;
        if (n < N_NODES) {
            g_Y0[n * COUTP + o] = a0[j];
            g_Y1[n * COUTP + o] = a1[j];
            g_Z [n * COUTP + o] = az[j] + b;   // pad cols exact 0
            g_A [n * COUTP + o] = 0.f;
        }
    }
}

// ---------------- flat edge scatter (proven): A[dst] += Y0[src] + u*Y1[src] ----------------
template<int COUTP>
__global__ void __launch_bounds__(256)
scatter_kernel(const int* __restrict__ ei, const float* __restrict__ ea)
{
    constexpr int Q = COUTP / 4;
    int idx = blockIdx.x * blockDim.x + threadIdx.x;
    if (idx >= N_EDGES * Q) return;
    int e = idx / Q;           // power-of-2 -> shift
    int q = idx - e * Q;

    int   s = ei[e];
    int   d = ei[N_EDGES + e];
    float u = ea[e];

    const float4* Y04 = reinterpret_cast<const float4*>(g_Y0);
    const float4* Y14 = reinterpret_cast<const float4*>(g_Y1);
    float4 v0 = Y04[s * Q + q];
    float4 v1 = Y14[s * Q + q];
    float4 m;
    m.x = fmaf(u, v1.x, v0.x);
    m.y = fmaf(u, v1.y, v0.y);
    m.z = fmaf(u, v1.z, v0.z);
    m.w = fmaf(u, v1.w, v0.w);

    float* dst = &g_A[d * COUTP + q * 4];
    asm volatile("red.global.add.v4.f32 [%0], {%1,%2,%3,%4};"
                 :: "l"(dst), "f"(m.x), "f"(m.y), "f"(m.z), "f"(m.w) : "memory");
}

// ---------------- epilogue: mean + residual (BN pre-folded) + ELU -> g_H ----------------
__global__ void __launch_bounds__(256)
epi_kernel()
{
    int i4 = blockIdx.x * blockDim.x + threadIdx.x;
    if (i4 >= N_NODES * (H_DIM / 4)) return;
    int n = i4 >> 4;

    int cnt = g_cnt[n];
    float inv = 1.f / (float)(cnt < 1 ? 1 : cnt);

    float4 a = reinterpret_cast<const float4*>(g_A)[i4];
    float4 z = reinterpret_cast<const float4*>(g_Z)[i4];

    float4 v;
    v.x = fmaf(a.x, inv, z.x);
    v.y = fmaf(a.y, inv, z.y);
    v.z = fmaf(a.z, inv, z.z);
    v.w = fmaf(a.w, inv, z.w);
    v.x = (v.x > 0.f) ? v.x : expm1f(v.x);
    v.y = (v.y > 0.f) ? v.y : expm1f(v.y);
    v.z = (v.z > 0.f) ? v.z : expm1f(v.z);
    v.w = (v.w > 0.f) ? v.w : expm1f(v.w);

    reinterpret_cast<float4*>(g_H)[i4] = v;
}

// ---------------- final: mean + residual + log_softmax (8 lanes per node) ----------------
__global__ void __launch_bounds__(256)
final_kernel(float* __restrict__ out)
{
    int t    = blockIdx.x * blockDim.x + threadIdx.x;
    int node = t >> 3;
    int o    = t & 7;
    if (node >= N_NODES) return;

    int cnt = g_cnt[node];
    float inv = 1.f / (float)(cnt < 1 ? 1 : cnt);
    float v = g_A[node * C_PAD + o] * inv + g_Z[node * C_PAD + o];

    float vm = (o < C_OUT) ? v : -INFINITY;
    float mx = vm;
    #pragma unroll
    for (int d = 1; d < 8; d <<= 1)
        mx = fmaxf(mx, __shfl_xor_sync(0xFFFFFFFFu, mx, d));

    float ex = (o < C_OUT) ? __expf(v - mx) : 0.f;
    float s  = ex;
    #pragma unroll
    for (int d = 1; d < 8; d <<= 1)
        s += __shfl_xor_sync(0xFFFFFFFFu, s, d);

    float lse = mx + logf(s);
    if (o < C_OUT) out[node * C_OUT + o] = v - lse;
}

// ---------------- launch ----------------
extern "C" void kernel_launch(void* const* d_in, const int* in_sizes, int n_in,
                              void* d_out, int out_size)
{
    const float* x   = (const float*)d_in[0];
    const int*   ei  = (const int*)  d_in[1];
    const float* ea  = (const float*)d_in[2];
    const float* W0  = (const float*)d_in[3];
    const float* R0  = (const float*)d_in[4];
    const float* B0  = (const float*)d_in[5];
    const float* W1  = (const float*)d_in[6];
    const float* R1  = (const float*)d_in[7];
    const float* B1  = (const float*)d_in[8];
    const float* W2  = (const float*)d_in[9];
    const float* R2  = (const float*)d_in[10];
    const float* B2  = (const float*)d_in[11];
    const float* G0  = (const float*)d_in[12];
    const float* BE0 = (const float*)d_in[13];
    const float* RM0 = (const float*)d_in[14];
    const float* RV0 = (const float*)d_in[15];
    const float* G1  = (const float*)d_in[16];
    const float* BE1 = (const float*)d_in[17];
    const float* RM1 = (const float*)d_in[18];
    const float* RV1 = (const float*)d_in[19];
    float* out = (float*)d_out;

    // prologue
    prep_kernel<<<(N_NODES + 255) / 256, 256>>>(W0, R0, B0, W1, R1, B1, W2, R2, B2,
                                                G0, BE0, RM0, RV0, G1, BE1, RM1, RV1);
    deg_kernel<<<(N_EDGES + 255) / 256, 256>>>(ei);

    // ---- Layer 0: input-space scatter (32-dim), then fused GEMM+mean+BN+ELU ----
    scatter_x_kernel<<<(N_EDGES * 8 + 255) / 256, 256>>>(ei, ea, x);
    gemm_l0_kernel<<<(N_NODES + 31) / 32, dim3(64, 4)>>>(x);

    // ---- Layer 1: 64 -> 64 (output-space) ----
    gemm3_kernel<64, 64, 64, 8><<<(N_NODES + 31) / 32, dim3(64, 4)>>>(1);
    scatter_kernel<64><<<(N_EDGES * 16 + 255) / 256, 256>>>(ei, ea);
    epi_kernel<<<(N_NODES * 16 + 255) / 256, 256>>>();

    // ---- Layer 2: 64 -> 7 (pad 8) ----
    gemm3_kernel<64, 7, 8, 2><<<(N_NODES + 63) / 64, dim3(8, 32)>>>(2);
    scatter_kernel<8><<<(N_EDGES * 2 + 255) / 256, 256>>>(ei, ea);
    final_kernel<<<(N_NODES * 8 + 255) / 256, 256>>>(out);
}

// round 16
// speedup vs baseline: 1.5923x; 1.0448x over previous
#include <cuda_runtime.h>
#include <cuda_fp16.h>
#include <math.h>

#define N_NODES 50000
#define N_EDGES 800000
#define F_IN    32
#define H_DIM   64
#define C_OUT   7
#define C_PAD   8
#define BN_EPS  1e-5f

// ---------------- scratch (device globals; no allocation) ----------------
__device__ __align__(128) __half2 g_Y01[N_NODES * H_DIM]; // per channel: (y0, y1) fp16
__device__ __align__(128) __half2 g_Xh [N_NODES * F_IN / 2]; // fp16 copy of x (message path)
__device__ __align__(128) float   g_Z [N_NODES * H_DIM];  // h @ (R*k) + bias'
__device__ __align__(128) float   g_A [N_NODES * H_DIM];  // aggregation accumulator (fp32)
__device__ __align__(128) float   g_H [N_NODES * H_DIM];  // hidden activations
__device__ __align__(128) float   g_ST[2 * N_NODES * F_IN];// L0 accumulators: S | T (fp32)
__device__ __align__(128) int     g_cnt[N_NODES];         // in-degree
// folded weights, PACKED layout per block: [cq][o][4]
__device__ __align__(16)  float g_WP0[3 * F_IN  * H_DIM];
__device__ __align__(16)  float g_WP1[3 * H_DIM * H_DIM];
__device__ __align__(16)  float g_WP2[3 * H_DIM * C_OUT];
__device__ __align__(16)  float g_TB0[H_DIM];
__device__ __align__(16)  float g_TB1[H_DIM];
__device__ __align__(16)  float g_TB2[C_OUT];

// ---------------- prep: zero g_cnt + fold BN + pack weights + fp16 x table ----------------
__device__ __forceinline__ void fold_one(const float* W, const float* R, const float* B,
                                         const float* G, const float* BE,
                                         const float* RM, const float* RV,
                                         float* WP, float* TB, int cin, int cout, int t)
{
    int c = t / cout, o = t % cout;
    float k = 1.f, sh = 0.f;
    if (G) {
        k  = G[o] * rsqrtf(RV[o] + BN_EPS);
        sh = BE[o] - RM[o] * k;
    }
    float w0 = W[c * cout + o];
    float w1 = W[cin * cout + c * cout + o];
    int pi = (c >> 2) * cout * 4 + o * 4 + (c & 3);
    WP[pi]                  = w0 * k;
    WP[cin * cout + pi]     = (w1 - w0) * k;
    WP[2 * cin * cout + pi] = R[c * cout + o] * k;
    if (c == 0) TB[o] = B[o] * k + sh;
}

__global__ void prep_kernel(const float* __restrict__ X,
                            const float* __restrict__ W0, const float* __restrict__ R0, const float* __restrict__ B0,
                            const float* __restrict__ W1, const float* __restrict__ R1, const float* __restrict__ B1,
                            const float* __restrict__ W2, const float* __restrict__ R2, const float* __restrict__ B2,
                            const float* __restrict__ G0, const float* __restrict__ BE0,
                            const float* __restrict__ RM0, const float* __restrict__ RV0,
                            const float* __restrict__ G1, const float* __restrict__ BE1,
                            const float* __restrict__ RM1, const float* __restrict__ RV1)
{
    int t = blockIdx.x * blockDim.x + threadIdx.x;
    if (t < N_NODES) {
        g_cnt[t] = 0;
        // fp16 copy of x row t (message path only)
        const float2* xr = reinterpret_cast<const float2*>(X + t * F_IN);
        #pragma unroll
        for (int i = 0; i < F_IN / 2; i++) {
            float2 f = xr[i];
            g_Xh[t * (F_IN / 2) + i] = __floats2half2_rn(f.x, f.y);
        }
    }

    const int S0 = F_IN * H_DIM;            // 2048
    const int S1 = S0 + H_DIM * H_DIM;      // 6144
    const int S2 = S1 + H_DIM * C_OUT;      // 6592
    if (t < S0) {
        fold_one(W0, R0, B0, G0, BE0, RM0, RV0, g_WP0, g_TB0, F_IN,  H_DIM, t);
    } else if (t < S1) {
        fold_one(W1, R1, B1, G1, BE1, RM1, RV1, g_WP1, g_TB1, H_DIM, H_DIM, t - S0);
    } else if (t < S2) {
        fold_one(W2, R2, B2, nullptr, nullptr, nullptr, nullptr, g_WP2, g_TB2, H_DIM, C_OUT, t - S1);
    }
}

// degree histogram + zero S/T (800k threads exactly cover the 800k float4 of g_ST)
__global__ void deg_kernel(const int* __restrict__ ei) {
    int e = blockIdx.x * blockDim.x + threadIdx.x;
    if (e < N_EDGES) {
        atomicAdd(&g_cnt[ei[N_EDGES + e]], 1);
        reinterpret_cast<float4*>(g_ST)[e] = make_float4(0.f, 0.f, 0.f, 0.f);
    }
}

// ---------------- L0 edge scatter (fp16 reads, fp32 atomics): S[d]+=x[s], T[d]+=u*x[s] ----------------
__global__ void __launch_bounds__(256)
scatter_x_kernel(const int* __restrict__ ei, const float* __restrict__ ea)
{
    constexpr int Q = F_IN / 4;   // 8
    int idx = blockIdx.x * blockDim.x + threadIdx.x;
    if (idx >= N_EDGES * Q) return;
    int e = idx >> 3;
    int q = idx & 7;

    int   s = ei[e];
    int   d = ei[N_EDGES + e];
    float u = ea[e];

    // channels 4q..4q+3 = two half2 = 8 bytes
    float2 raw = reinterpret_cast<const float2*>(g_Xh)[s * Q + q];
    const __half2* hp = reinterpret_cast<const __half2*>(&raw);
    float2 p0 = __half22float2(hp[0]);
    float2 p1 = __half22float2(hp[1]);

    float4 v = make_float4(p0.x, p0.y, p1.x, p1.y);
    float4 t;
    t.x = u * v.x; t.y = u * v.y; t.z = u * v.z; t.w = u * v.w;

    float* ps = &g_ST[d * F_IN + q * 4];
    float* pt = &g_ST[N_NODES * F_IN + d * F_IN + q * 4];
    asm volatile("red.global.add.v4.f32 [%0], {%1,%2,%3,%4};"
                 :: "l"(ps), "f"(v.x), "f"(v.y), "f"(v.z), "f"(v.w) : "memory");
    asm volatile("red.global.add.v4.f32 [%0], {%1,%2,%3,%4};"
                 :: "l"(pt), "f"(t.x), "f"(t.y), "f"(t.z), "f"(t.w) : "memory");
}

// ---------------- L0 fused node GEMM: h = ELU(S'@W0k + T'@dWk + x@Rk + b) ----------------
__global__ void __launch_bounds__(256)
gemm_l0_kernel(const float* __restrict__ X)
{
    __shared__ float ss[32][F_IN];
    __shared__ float st[32][F_IN];
    __shared__ float sx[32][F_IN];

    int nbase = blockIdx.x * 32;
    int tid = threadIdx.y * 64 + threadIdx.x;

    const float4* S4 = reinterpret_cast<const float4*>(g_ST);
    const float4* T4 = reinterpret_cast<const float4*>(g_ST + N_NODES * F_IN);
    const float4* X4 = reinterpret_cast<const float4*>(X);
    {
        int row = tid >> 3, q = tid & 7;
        int n = nbase + row;
        float4 vs = make_float4(0.f,0.f,0.f,0.f), vt = vs, vx = vs;
        if (n < N_NODES) {
            int cnt = g_cnt[n];
            float inv = 1.f / (float)(cnt < 1 ? 1 : cnt);
            vs = S4[n * 8 + q];
            vt = T4[n * 8 + q];
            vx = X4[n * 8 + q];
            vs.x *= inv; vs.y *= inv; vs.z *= inv; vs.w *= inv;
            vt.x *= inv; vt.y *= inv; vt.z *= inv; vt.w *= inv;
        }
        *reinterpret_cast<float4*>(&ss[row][q * 4]) = vs;
        *reinterpret_cast<float4*>(&st[row][q * 4]) = vt;
        *reinterpret_cast<float4*>(&sx[row][q * 4]) = vx;
    }
    __syncthreads();

    int o  = threadIdx.x;          // 0..63
    int nb = threadIdx.y * 8;      // 8 nodes per thread

    float a[8];
    #pragma unroll
    for (int j = 0; j < 8; j++) a[j] = 0.f;

    const float4* w0p = reinterpret_cast<const float4*>(g_WP0);
    const float4* dwp = reinterpret_cast<const float4*>(g_WP0 + H_DIM * F_IN);
    const float4* rp  = reinterpret_cast<const float4*>(g_WP0 + 2 * H_DIM * F_IN);

    #pragma unroll
    for (int cq = 0; cq < F_IN / 4; cq++) {
        float4 w0 = w0p[cq * H_DIM + o];
        float4 dw = dwp[cq * H_DIM + o];
        float4 r  = rp [cq * H_DIM + o];
        #pragma unroll
        for (int j = 0; j < 8; j++) {
            float4 s4 = *reinterpret_cast<const float4*>(&ss[nb + j][cq * 4]);
            float4 t4 = *reinterpret_cast<const float4*>(&st[nb + j][cq * 4]);
            float4 x4 = *reinterpret_cast<const float4*>(&sx[nb + j][cq * 4]);
            float acc = a[j];
            acc = fmaf(s4.x, w0.x, acc); acc = fmaf(s4.y, w0.y, acc);
            acc = fmaf(s4.z, w0.z, acc); acc = fmaf(s4.w, w0.w, acc);
            acc = fmaf(t4.x, dw.x, acc); acc = fmaf(t4.y, dw.y, acc);
            acc = fmaf(t4.z, dw.z, acc); acc = fmaf(t4.w, dw.w, acc);
            acc = fmaf(x4.x, r.x,  acc); acc = fmaf(x4.y, r.y,  acc);
            acc = fmaf(x4.z, r.z,  acc); acc = fmaf(x4.w, r.w,  acc);
            a[j] = acc;
        }
    }

    float b = g_TB0[o];
    #pragma unroll
    for (int j = 0; j < 8; j++) {
        int n = nbase + nb + j;
        if (n < N_NODES) {
            float v = a[j] + b;
            v = (v > 0.f) ? v : expm1f(v);
            g_H[n * H_DIM + o] = v;
        }
    }
}

// ---------------- fused node GEMM: Y01 (fp16 pair), Z; zeroes g_A ----------------
template<int CIN, int COUT, int COUTP, int NT>
__global__ void __launch_bounds__(256)
gemm3_kernel(int sel)
{
    constexpr int TY    = 256 / COUTP;
    constexpr int NODES = TY * NT;
    __shared__ float sx[NODES][CIN];

    const float* WP = (sel == 1) ? g_WP1 : g_WP2;
    const float* TB = (sel == 1) ? g_TB1 : g_TB2;
    const float* X  = (const float*)g_H;

    int nbase = blockIdx.x * NODES;
    int tid = threadIdx.y * COUTP + threadIdx.x;

    constexpr int NV = NODES * CIN / 4;
    const float4* X4 = reinterpret_cast<const float4*>(X);
    float4* sx4 = reinterpret_cast<float4*>(&sx[0][0]);
    #pragma unroll
    for (int i = tid; i < NV; i += 256) {
        int nn = nbase + i / (CIN / 4);
        float4 v = make_float4(0.f, 0.f, 0.f, 0.f);
        if (nn < N_NODES) v = X4[nn * (CIN / 4) + (i % (CIN / 4))];
        sx4[i] = v;
    }
    __syncthreads();

    int o  = threadIdx.x;
    int nb = threadIdx.y * NT;

    float a0[NT], a1[NT], az[NT];
    #pragma unroll
    for (int j = 0; j < NT; j++) { a0[j] = 0.f; a1[j] = 0.f; az[j] = 0.f; }

    float b = 0.f;
    if (o < COUT) {
        b = TB[o];
        const float4* w0p = reinterpret_cast<const float4*>(WP);
        const float4* dwp = reinterpret_cast<const float4*>(WP + CIN * COUT);
        const float4* rp  = reinterpret_cast<const float4*>(WP + 2 * CIN * COUT);
        #pragma unroll 4
        for (int cq = 0; cq < CIN / 4; cq++) {
            float4 w0 = w0p[cq * COUT + o];
            float4 dw = dwp[cq * COUT + o];
            float4 r  = rp [cq * COUT + o];
            #pragma unroll
            for (int j = 0; j < NT; j++) {
                float4 xv = *reinterpret_cast<const float4*>(&sx[nb + j][cq * 4]);
                float c0 = a0[j], c1 = a1[j], cz = az[j];
                c0 = fmaf(xv.x, w0.x, c0); c0 = fmaf(xv.y, w0.y, c0);
                c0 = fmaf(xv.z, w0.z, c0); c0 = fmaf(xv.w, w0.w, c0);
                c1 = fmaf(xv.x, dw.x, c1); c1 = fmaf(xv.y, dw.y, c1);
                c1 = fmaf(xv.z, dw.z, c1); c1 = fmaf(xv.w, dw.w, c1);
                cz = fmaf(xv.x, r.x,  cz); cz = fmaf(xv.y, r.y,  cz);
                cz = fmaf(xv.z, r.z,  cz); cz = fmaf(xv.w, r.w,  cz);
                a0[j] = c0; a1[j] = c1; az[j] = cz;
            }
        }
    }

    #pragma unroll
    for (int j = 0; j < NT; j++) {
        int n = nbase + nb + j;
        if (n < N_NODES) {
            g_Y01[n * COUTP + o] = __floats2half2_rn(a0[j], a1[j]);
            g_Z  [n * COUTP + o] = az[j] + b;   // pad cols exact 0
            g_A  [n * COUTP + o] = 0.f;
        }
    }
}

// ---------------- flat edge scatter (fp16 reads, fp32 atomics) ----------------
template<int COUTP>
__global__ void __launch_bounds__(256)
scatter_kernel(const int* __restrict__ ei, const float* __restrict__ ea)
{
    constexpr int Q = COUTP / 4;
    int idx = blockIdx.x * blockDim.x + threadIdx.x;
    if (idx >= N_EDGES * Q) return;
    int e = idx / Q;           // power-of-2 -> shift
    int q = idx - e * Q;

    int   s = ei[e];
    int   d = ei[N_EDGES + e];
    float u = ea[e];

    // 4 channels = 4 half2 pairs (y0,y1) = 16 bytes, one LDG.128
    float4 raw = reinterpret_cast<const float4*>(g_Y01)[s * Q + q];
    const __half2* hp = reinterpret_cast<const __half2*>(&raw);
    float2 p0 = __half22float2(hp[0]);
    float2 p1 = __half22float2(hp[1]);
    float2 p2 = __half22float2(hp[2]);
    float2 p3 = __half22float2(hp[3]);

    float4 m;
    m.x = fmaf(u, p0.y, p0.x);
    m.y = fmaf(u, p1.y, p1.x);
    m.z = fmaf(u, p2.y, p2.x);
    m.w = fmaf(u, p3.y, p3.x);

    float* dst = &g_A[d * COUTP + q * 4];
    asm volatile("red.global.add.v4.f32 [%0], {%1,%2,%3,%4};"
                 :: "l"(dst), "f"(m.x), "f"(m.y), "f"(m.z), "f"(m.w) : "memory");
}

// ---------------- epilogue: mean + residual (BN pre-folded) + ELU -> g_H ----------------
__global__ void __launch_bounds__(256)
epi_kernel()
{
    int i4 = blockIdx.x * blockDim.x + threadIdx.x;
    if (i4 >= N_NODES * (H_DIM / 4)) return;
    int n = i4 >> 4;

    int cnt = g_cnt[n];
    float inv = 1.f / (float)(cnt < 1 ? 1 : cnt);

    float4 a = reinterpret_cast<const float4*>(g_A)[i4];
    float4 z = reinterpret_cast<const float4*>(g_Z)[i4];

    float4 v;
    v.x = fmaf(a.x, inv, z.x);
    v.y = fmaf(a.y, inv, z.y);
    v.z = fmaf(a.z, inv, z.z);
    v.w = fmaf(a.w, inv, z.w);
    v.x = (v.x > 0.f) ? v.x : expm1f(v.x);
    v.y = (v.y > 0.f) ? v.y : expm1f(v.y);
    v.z = (v.z > 0.f) ? v.z : expm1f(v.z);
    v.w = (v.w > 0.f) ? v.w : expm1f(v.w);

    reinterpret_cast<float4*>(g_H)[i4] = v;
}

// ---------------- final: mean + residual + log_softmax (8 lanes per node) ----------------
__global__ void __launch_bounds__(256)
final_kernel(float* __restrict__ out)
{
    int t    = blockIdx.x * blockDim.x + threadIdx.x;
    int node = t >> 3;
    int o    = t & 7;
    if (node >= N_NODES) return;

    int cnt = g_cnt[node];
    float inv = 1.f / (float)(cnt < 1 ? 1 : cnt);
    float v = g_A[node * C_PAD + o] * inv + g_Z[node * C_PAD + o];

    float vm = (o < C_OUT) ? v : -INFINITY;
    float mx = vm;
    #pragma unroll
    for (int d = 1; d < 8; d <<= 1)
        mx = fmaxf(mx, __shfl_xor_sync(0xFFFFFFFFu, mx, d));

    float ex = (o < C_OUT) ? __expf(v - mx) : 0.f;
    float s  = ex;
    #pragma unroll
    for (int d = 1; d < 8; d <<= 1)
        s += __shfl_xor_sync(0xFFFFFFFFu, s, d);

    float lse = mx + logf(s);
    if (o < C_OUT) out[node * C_OUT + o] = v - lse;
}

// ---------------- launch ----------------
extern "C" void kernel_launch(void* const* d_in, const int* in_sizes, int n_in,
                              void* d_out, int out_size)
{
    const float* x   = (const float*)d_in[0];
    const int*   ei  = (const int*)  d_in[1];
    const float* ea  = (const float*)d_in[2];
    const float* W0  = (const float*)d_in[3];
    const float* R0  = (const float*)d_in[4];
    const float* B0  = (const float*)d_in[5];
    const float* W1  = (const float*)d_in[6];
    const float* R1  = (const float*)d_in[7];
    const float* B1  = (const float*)d_in[8];
    const float* W2  = (const float*)d_in[9];
    const float* R2  = (const float*)d_in[10];
    const float* B2  = (const float*)d_in[11];
    const float* G0  = (const float*)d_in[12];
    const float* BE0 = (const float*)d_in[13];
    const float* RM0 = (const float*)d_in[14];
    const float* RV0 = (const float*)d_in[15];
    const float* G1  = (const float*)d_in[16];
    const float* BE1 = (const float*)d_in[17];
    const float* RM1 = (const float*)d_in[18];
    const float* RV1 = (const float*)d_in[19];
    float* out = (float*)d_out;

    // prologue
    prep_kernel<<<(N_NODES + 255) / 256, 256>>>(x, W0, R0, B0, W1, R1, B1, W2, R2, B2,
                                                G0, BE0, RM0, RV0, G1, BE1, RM1, RV1);
    deg_kernel<<<(N_EDGES + 255) / 256, 256>>>(ei);

    // ---- Layer 0: input-space scatter (fp16 gather), then fused GEMM+mean+BN+ELU ----
    scatter_x_kernel<<<(N_EDGES * 8 + 255) / 256, 256>>>(ei, ea);
    gemm_l0_kernel<<<(N_NODES + 31) / 32, dim3(64, 4)>>>(x);

    // ---- Layer 1: 64 -> 64 ----
    gemm3_kernel<64, 64, 64, 8><<<(N_NODES + 31) / 32, dim3(64, 4)>>>(1);
    scatter_kernel<64><<<(N_EDGES * 16 + 255) / 256, 256>>>(ei, ea);
    epi_kernel<<<(N_NODES * 16 + 255) / 256, 256>>>();

    // ---- Layer 2: 64 -> 7 (pad 8) ----
    gemm3_kernel<64, 7, 8, 2><<<(N_NODES + 63) / 64, dim3(8, 32)>>>(2);
    scatter_kernel<8><<<(N_EDGES * 2 + 255) / 256, 256>>>(ei, ea);
    final_kernel<<<(N_NODES * 8 + 255) / 256, 256>>>(out);
}